// round 16
// baseline (speedup 1.0000x reference)
#include <cuda_runtime.h>
#include <cuda_bf16.h>

#define NKC 5000
#define BB  512
#define TT  100
#define THREADS 256
#define NBUILD 128        // builder blocks
#define TBL_SLICE 40      // entries per builder block (128*40 >= 5000)

#define BAR_COMPUTE(n) asm volatile("bar.sync 1, %0;" :: "r"(n) : "memory")
#define BAR_COPY(n)    asm volatile("bar.sync 2, %0;" :: "r"(n) : "memory")

__device__ float g_c4[NKC];   // sigmoid(logits[:,4]) — default state
__device__ int   g_ready;    // builder blocks that published their slice
__device__ int   g_done;     // blocks finished (reset)

// sigmoid via single-MUFU tanh.approx: s = 0.5 + 0.5*tanh(x/2)
__device__ __forceinline__ float sigmoidf(float x) {
    float t;
    asm("tanh.approx.f32 %0, %1;" : "=f"(t) : "f"(0.5f * x));
    return fmaf(0.5f, t, 0.5f);
}

__global__ __launch_bounds__(THREADS, 4)
void fused_kernel(const int* __restrict__ prev_kc,
                  const int* __restrict__ curr_kc,
                  const int* __restrict__ prev_corr,
                  const float* __restrict__ logits,
                  float* __restrict__ out)
{
    __shared__ int   sPK[TT];
    __shared__ int   sPW[TT];
    __shared__ float sVal[TT];
    __shared__ int   sNotLast[TT];
    __shared__ int   sMaxD;

    const int b   = blockIdx.x;
    const int tid = threadIdx.x;

    float* __restrict__ orow = out + (size_t)BB * TT + (size_t)b * NKC;

    int   pk = -1, ck = -1, c = 0;
    float myVal = 0.f;

    if (tid >= 128) {
        // ================= COPY GROUP (warps 4-7) =================
        // builder blocks: warp 4 builds 40-entry slice; then spin; then copy.
        if (b < NBUILD && tid < 160) {
            const int lane = tid - 128;
            const int k = b * TBL_SLICE + lane;
            if (k < NKC)
                g_c4[k] = sigmoidf(logits[k * 5 + 4]);
            if (lane < TBL_SLICE - 32) {
                const int k2 = k + 32;
                if (k2 < NKC)
                    g_c4[k2] = sigmoidf(logits[k2 * 5 + 4]);
            }
            __threadfence();
            __syncwarp();
            if (tid == 128)
                atomicAdd(&g_ready, 1);
        }

        if (tid == 160) {                      // copy-group spinner (warp 5)
            while (*(volatile int*)&g_ready < NBUILD)
                __nanosleep(20);
            __threadfence();
        }
        BAR_COPY(128);

        // bulk copy with MLP=10: all loads issued before any store
        {
            const float4* __restrict__ src = (const float4*)g_c4;
            float4*       __restrict__ dst = (float4*)orow;
            const int base = tid - 128;
            float4 v[10];
            #pragma unroll
            for (int u = 0; u < 10; u++) {
                const int i = base + u * 128;
                if (i < NKC / 4) v[u] = src[i];
            }
            #pragma unroll
            for (int u = 0; u < 10; u++) {
                const int i = base + u * 128;
                if (i < NKC / 4) dst[i] = v[u];
            }
        }
    } else {
        // ================= SOLVER GROUP (warps 0-3) =================
        // fully independent of the table: inline tanh sigmoids, no spin.
        if (tid == 0) sMaxD = 0;
        float l_p0 = 0.f, l_p1 = 0.f, l_p2 = 0.f, l_p3 = 0.f, l_p4 = 0.f;
        float l_c2 = 0.f, l_c3 = 0.f, l_c4 = 0.f;
        if (tid < TT) {
            ck = curr_kc[b * TT + tid];
            pk = prev_kc[b * TT + tid];
            c  = prev_corr[b * TT + tid];
            sPK[tid]      = (tid >= 1) ? pk : -9;   // step 0 performs no update
            sNotLast[tid] = 0;
            // issue raw logits loads NOW; scan hides their latency
            l_c2 = logits[ck * 5 + 2];
            l_c3 = logits[ck * 5 + 3];
            l_c4 = logits[ck * 5 + 4];
            if (tid >= 1) {
                l_p0 = logits[pk * 5 + 0];
                l_p1 = logits[pk * 5 + 1];
                l_p2 = logits[pk * 5 + 2];
                l_p3 = logits[pk * 5 + 3];
                l_p4 = logits[pk * 5 + 4];
            }
        }
        BAR_COMPUTE(128);

        // predecessor-only dependency scan (avg 12.5 int4 iters)
        int pw = -1, w = -1;
        if (tid < TT) {
            const int4* sp4 = (const int4*)sPK;
            const int jmax = tid >> 2;
            for (int j = 0; j <= jmax; j++) {
                const int4 v = sp4[j];
                const int s0 = 4 * j;
                if (v.x == pk && s0     < tid) pw = s0;
                if (v.y == pk && s0 + 1 < tid) pw = s0 + 1;
                if (v.z == pk && s0 + 2 < tid) pw = s0 + 2;
                if (v.w == pk && s0 + 3 < tid) pw = s0 + 3;
                if (v.x == ck && s0     <= tid) w = s0;
                if (v.y == ck && s0 + 1 <= tid) w = s0 + 1;
                if (v.z == ck && s0 + 2 <= tid) w = s0 + 2;
                if (v.w == ck && s0 + 3 <= tid) w = s0 + 3;
            }
            sPW[tid] = pw;
            if (pw >= 0) sNotLast[pw] = 1;     // pw values distinct -> plain store
        }
        BAR_COMPUTE(128);

        // chain depth via pointer chase (depth ~1-4)
        int depth = 0;
        if (tid >= 1 && tid < TT) {
            int j = pw;
            while (j >= 0) { j = sPW[j]; depth++; }
            atomicMax(&sMaxD, depth);
        }

        // constants from already-loaded raw logits (8 cheap MUFU tanh)
        float A = 0.f, Bc = 0.f, P0 = 0.f, E = 0.f, F = 0.f, G = 0.f;
        float initSkill = 0.f, initCs = 0.f;
        if (tid < TT) {
            const float c2 = sigmoidf(l_c2);
            const float c3 = sigmoidf(l_c3);
            G = c2;
            F = c3 - c2;
            initCs = sigmoidf(l_c4);
            if (tid >= 1) {
                const float p0 = sigmoidf(l_p0);
                const float p1 = sigmoidf(l_p1);
                const float p2 = sigmoidf(l_p2);
                const float p3 = sigmoidf(l_p3);
                A  = c ? p3 : (1.0f - p3);     // p_out[:,1]
                Bc = c ? p2 : (1.0f - p2);     // p_out[:,0]
                P0 = p0;
                E  = 1.0f - p1 - p0;
                initSkill = sigmoidf(l_p4);
            }
        }
        BAR_COMPUTE(128);                      // publishes sMaxD
        const int maxD = sMaxD;

        // wavefront by depth: one group barrier per round
        for (int r = 0; r < maxD; r++) {
            if (tid >= 1 && tid < TT && depth == r) {
                const float skill = (r == 0) ? initSkill : sVal[pw];
                const float num   = A * skill;
                const float den   = fmaf(Bc, -skill, Bc) + num;  // B*(1-skill)+A*skill
                const float filt  = __fdividef(num, den);
                myVal = fmaf(E, filt, P0);
                sVal[tid] = myVal;
            }
            BAR_COMPUTE(128);
        }
        // last round: no trailing group barrier (join __syncthreads covers it)
        if (tid >= 1 && tid < TT && depth == maxD) {
            const float skill = (maxD == 0) ? initSkill : sVal[pw];
            const float num   = A * skill;
            const float den   = fmaf(Bc, -skill, Bc) + num;
            const float filt  = __fdividef(num, den);
            myVal = fmaf(E, filt, P0);
            sVal[tid] = myVal;
        }
        BAR_COMPUTE(128);

        // probs output
        if (tid < TT) {
            const float cs = (w < 0) ? initCs : sVal[w];
            out[b * TT + tid] = fmaf(F, cs, G);
        }
    }

    // ---- join: copy complete + values complete, then sparse patch ----
    __syncthreads();
    if (tid >= 1 && tid < TT && !sNotLast[tid])
        orow[pk] = myVal;

    // ---- counter reset for next graph replay ----
    if (tid == 0) {
        const int d = atomicAdd(&g_done, 1);
        if (d == BB - 1) {          // last block: everyone has passed the spin
            g_ready = 0;
            g_done  = 0;
        }
    }
}

extern "C" void kernel_launch(void* const* d_in, const int* in_sizes, int n_in,
                              void* d_out, int out_size) {
    const int*   prev_kc   = (const int*)d_in[0];
    const int*   curr_kc   = (const int*)d_in[1];
    const int*   prev_corr = (const int*)d_in[2];
    const float* kc_logits = (const float*)d_in[3];
    float*       out       = (float*)d_out;

    fused_kernel<<<BB, THREADS>>>(prev_kc, curr_kc, prev_corr, kc_logits, out);
}

// round 17
// speedup vs baseline: 1.2609x; 1.2609x over previous
#include <cuda_runtime.h>
#include <cuda_bf16.h>

#define NKC 5000
#define BB  512
#define TT  100
#define THREADS 256
#define TBL_SLICE 10   // g_c4 entries built per block (512*10 >= 5000)
#define HALF (BB / 2)

#define BAR_COMPUTE(n) asm volatile("bar.sync 1, %0;" :: "r"(n) : "memory")
#define BAR_COPY(n)    asm volatile("bar.sync 2, %0;" :: "r"(n) : "memory")

__device__ float g_c4[NKC];    // sigmoid(logits[:,4]) — default state
__device__ int   g_ready0;    // builder arrivals, blocks 0..255   (entries < 2560)
__device__ int   g_ready1;    // builder arrivals, blocks 256..511 (entries >= 2560)
__device__ int   g_done;      // blocks finished (reset)

// sigmoid via single-MUFU tanh.approx: s = 0.5 + 0.5*tanh(x/2)
__device__ __forceinline__ float sigmoidf(float x) {
    float t;
    asm("tanh.approx.f32 %0, %1;" : "=f"(t) : "f"(0.5f * x));
    return fmaf(0.5f, t, 0.5f);
}

__global__ __launch_bounds__(THREADS, 4)
void fused_kernel(const int* __restrict__ prev_kc,
                  const int* __restrict__ curr_kc,
                  const int* __restrict__ prev_corr,
                  const float* __restrict__ logits,
                  float* __restrict__ out)
{
    __shared__ int   sPK[TT];
    __shared__ int   sPW[TT];
    __shared__ float sVal[TT];
    __shared__ int   sNotLast[TT];
    __shared__ int   sMaxD;

    const int b   = blockIdx.x;
    const int tid = threadIdx.x;

    float* __restrict__ orow = out + (size_t)BB * TT + (size_t)b * NKC;

    int   pk = -1, ck = -1, c = 0;
    float myVal = 0.f;

    if (tid >= 128) {
        // ================= COPY GROUP (warps 4-7) =================
        // build g_c4 slice -> arrive -> pipelined spin+copy (two halves).
        if (tid < 128 + TBL_SLICE) {
            const int k = b * TBL_SLICE + (tid - 128);
            if (k < NKC)
                g_c4[k] = sigmoidf(logits[k * 5 + 4]);
            __threadfence();
        }
        __syncwarp();                          // warp 4: builders done
        if (tid == 128)
            atomicAdd((b < HALF) ? &g_ready0 : &g_ready1, 1);

        const float4* __restrict__ src = (const float4*)g_c4;
        float4*       __restrict__ dst = (float4*)orow;
        const int base = tid - 128;
        float4 v[5];

        // ---- half 0: entries [0, 2560) ----
        if (tid == 160) {                      // copy-group spinner (warp 5)
            while (*(volatile int*)&g_ready0 < HALF)
                __nanosleep(20);
            __threadfence();
        }
        BAR_COPY(128);
        #pragma unroll
        for (int u = 0; u < 5; u++)
            v[u] = src[base + u * 128];        // max idx 639 < 640
        #pragma unroll
        for (int u = 0; u < 5; u++)
            dst[base + u * 128] = v[u];

        // ---- half 1: entries [2560, 5000) ----
        if (tid == 160) {
            while (*(volatile int*)&g_ready1 < HALF)
                __nanosleep(20);
            __threadfence();
        }
        BAR_COPY(128);
        #pragma unroll
        for (int u = 5; u < 10; u++) {
            const int i = base + u * 128;
            if (i < NKC / 4) v[u - 5] = src[i];
        }
        #pragma unroll
        for (int u = 5; u < 10; u++) {
            const int i = base + u * 128;
            if (i < NKC / 4) dst[i] = v[u - 5];
        }
    } else {
        // ================= SOLVER GROUP (warps 0-3) =================
        // fully independent: inline sigmoids, no table, no global spin.
        if (tid == 0) sMaxD = 0;
        if (tid < TT) {
            ck = curr_kc[b * TT + tid];
            pk = prev_kc[b * TT + tid];
            c  = prev_corr[b * TT + tid];
            sPK[tid]      = (tid >= 1) ? pk : -9;   // step 0 performs no update
            sNotLast[tid] = 0;
        }
        BAR_COMPUTE(128);

        // predecessor-only dependency scan (avg 12.5 int4 iters)
        int pw = -1, w = -1;
        if (tid < TT) {
            const int4* sp4 = (const int4*)sPK;
            const int jmax = tid >> 2;
            for (int j = 0; j <= jmax; j++) {
                const int4 v = sp4[j];
                const int s0 = 4 * j;
                if (v.x == pk && s0     < tid) pw = s0;
                if (v.y == pk && s0 + 1 < tid) pw = s0 + 1;
                if (v.z == pk && s0 + 2 < tid) pw = s0 + 2;
                if (v.w == pk && s0 + 3 < tid) pw = s0 + 3;
                if (v.x == ck && s0     <= tid) w = s0;
                if (v.y == ck && s0 + 1 <= tid) w = s0 + 1;
                if (v.z == ck && s0 + 2 <= tid) w = s0 + 2;
                if (v.w == ck && s0 + 3 <= tid) w = s0 + 3;
            }
            sPW[tid] = pw;
            if (pw >= 0) sNotLast[pw] = 1;     // pw values distinct -> plain store
        }
        BAR_COMPUTE(128);

        // chain depth via pointer chase (depth ~1-4)
        int depth = 0;
        if (tid >= 1 && tid < TT) {
            int j = pw;
            while (j >= 0) { j = sPW[j]; depth++; }
            atomicMax(&sMaxD, depth);
        }

        // inline constants (8 MUFU tanh per thread, overlapped with chase)
        float A = 0.f, Bc = 0.f, P0 = 0.f, E = 0.f, F = 0.f, G = 0.f;
        float initSkill = 0.f, initCs = 0.f;
        if (tid < TT) {
            const float c2 = sigmoidf(logits[ck * 5 + 2]);
            const float c3 = sigmoidf(logits[ck * 5 + 3]);
            G = c2;
            F = c3 - c2;
            initCs = sigmoidf(logits[ck * 5 + 4]);
            if (tid >= 1) {
                const float p0 = sigmoidf(logits[pk * 5 + 0]);
                const float p1 = sigmoidf(logits[pk * 5 + 1]);
                const float p2 = sigmoidf(logits[pk * 5 + 2]);
                const float p3 = sigmoidf(logits[pk * 5 + 3]);
                A  = c ? p3 : (1.0f - p3);     // p_out[:,1]
                Bc = c ? p2 : (1.0f - p2);     // p_out[:,0]
                P0 = p0;
                E  = 1.0f - p1 - p0;
                initSkill = sigmoidf(logits[pk * 5 + 4]);
            }
        }
        BAR_COMPUTE(128);                      // publishes sMaxD
        const int maxD = sMaxD;

        // wavefront by depth: one group barrier per round
        for (int r = 0; r <= maxD; r++) {
            if (tid >= 1 && tid < TT && depth == r) {
                const float skill = (r == 0) ? initSkill : sVal[pw];
                const float num   = A * skill;
                const float den   = fmaf(Bc, -skill, Bc) + num;  // B*(1-skill)+A*skill
                const float filt  = __fdividef(num, den);
                myVal = fmaf(E, filt, P0);
                sVal[tid] = myVal;
            }
            BAR_COMPUTE(128);
        }

        // probs output
        if (tid < TT) {
            const float cs = (w < 0) ? initCs : sVal[w];
            out[b * TT + tid] = fmaf(F, cs, G);
        }
    }

    // ---- join: copy complete + values complete, then sparse patch ----
    __syncthreads();
    if (tid >= 1 && tid < TT && !sNotLast[tid])
        orow[pk] = myVal;

    // ---- counter reset for next graph replay ----
    if (tid == 0) {
        const int d = atomicAdd(&g_done, 1);
        if (d == BB - 1) {          // last block: everyone has passed both spins
            g_ready0 = 0;
            g_ready1 = 0;
            g_done   = 0;
        }
    }
}

extern "C" void kernel_launch(void* const* d_in, const int* in_sizes, int n_in,
                              void* d_out, int out_size) {
    const int*   prev_kc   = (const int*)d_in[0];
    const int*   curr_kc   = (const int*)d_in[1];
    const int*   prev_corr = (const int*)d_in[2];
    const float* kc_logits = (const float*)d_in[3];
    float*       out       = (float*)d_out;

    fused_kernel<<<BB, THREADS>>>(prev_kc, curr_kc, prev_corr, kc_logits, out);
}